// round 9
// baseline (speedup 1.0000x reference)
#include <cuda_runtime.h>
#include <cuda_bf16.h>
#include <cstdint>

#define BB 128
#define TT 100
#define NN 2048
#define OO 512
#define DLY 10

#define ALPHA_F   0.90483741803595957316f   // exp(-1/10)
#define DEC_F     0.95122942450071400910f   // exp(-1/20)
#define CDEC_F    0.04877057549928599090f   // 1 - exp(-1/20)
#define THRESH_F  0.02f
#define A_PLUS_F  1e-4f
#define A_MINUS_F 1e-4f
#define INVB_F    0.0078125f                // 1/128, exact

#define SPLIT_A 16          // hw K-chunks of 128 (K=2048)
#define SPLIT_I 4           // iew K-chunks of 128 (K=512)
#define NBLK 160            // persistent grid size (all co-resident)

typedef __nv_bfloat16 bf16;

// ---------------- state (static device globals; no allocation) ----------------
__device__ bf16  g_l1b [(size_t)TT*BB*NN];
__device__ bf16  g_tr1h[(size_t)TT*BB*NN];
__device__ bf16  g_tr1l[(size_t)TT*BB*NN];
__device__ float g_v2 [BB*OO];
__device__ float g_vi [BB*OO];
__device__ float g_tr2[BB*OO];
__device__ float g_tri[BB*OO];
__device__ bf16  g_tr2h[BB*OO], g_tr2l[BB*OO];
__device__ bf16  g_trih[BB*OO], g_tril[BB*OO];
__device__ bf16  g_bufb[BB*DLY*OO];
__device__ float g_hw [(size_t)OO*NN];
__device__ bf16  g_hwh[(size_t)OO*NN], g_hwm[(size_t)OO*NN], g_hwl[(size_t)OO*NN];
__device__ float g_iew[OO*OO];
__device__ bf16  g_iewh[OO*OO], g_iewm[OO*OO], g_iewl[OO*OO];
__device__ float g_ediag[OO];
__device__ float g_mtr2[OO];
__device__ float g_pA[SPLIT_A*BB*OO];
__device__ float g_pI[SPLIT_I*BB*OO];
__device__ int   g_nzcnt[NN];
__device__ int   g_nzcol[(size_t)NN*NN];
__device__ float g_nzval[(size_t)NN*NN];
__device__ int   g_bar;                       // grid barrier counter (reset at kernel end)

__device__ __forceinline__ void split3(float w, bf16& h, bf16& m, bf16& l) {
    h = __float2bfloat16(w);
    float r1 = __fadd_rn(w, -__bfloat162float(h));
    m = __float2bfloat16(r1);
    float r2 = __fadd_rn(r1, -__bfloat162float(m));
    l = __float2bfloat16(r2);
}
__device__ __forceinline__ void split2(float w, bf16& h, bf16& l) {
    h = __float2bfloat16(w);
    l = __float2bfloat16(__fadd_rn(w, -__bfloat162float(h)));
}
__device__ __forceinline__ uint32_t s2u(const void* p) {
    return (uint32_t)__cvta_generic_to_shared(p);
}
__device__ __forceinline__ void cpa16(uint32_t d, const void* s) {
    asm volatile("cp.async.ca.shared.global [%0], [%1], 16;\n" :: "r"(d), "l"(s));
}
__device__ __forceinline__ void cpa_commit_wait() {
    asm volatile("cp.async.commit_group;\n");
    asm volatile("cp.async.wait_group 0;\n");
}

// grid barrier: release-fence all threads, arrive, spin, acquire-fence (CCTL.IVALL flushes L1)
__device__ __forceinline__ void gridbar(int& gen) {
    __threadfence();
    __syncthreads();
    gen++;
    if (threadIdx.x == 0) {
        atomicAdd(&g_bar, 1);
        int target = gen * NBLK;
        while (*((volatile int*)&g_bar) < target) __nanosleep(64);
        __threadfence();
    }
    __syncthreads();
}

// ---------------- init ----------------
__global__ void k_init(const float* __restrict__ hw_in,
                       const float* __restrict__ eiw_in,
                       const float* __restrict__ iew_in) {
    int i = blockIdx.x * blockDim.x + threadIdx.x;
    if (i < OO*NN) {
        float w = hw_in[i];
        g_hw[i] = w;
        split3(w, g_hwh[i], g_hwm[i], g_hwl[i]);
    }
    if (i < BB*DLY*OO) g_bufb[i] = __float2bfloat16(0.f);
    if (i < BB*OO) {
        g_v2[i]=0.f; g_vi[i]=0.f; g_tr2[i]=0.f; g_tri[i]=0.f;
        bf16 z = __float2bfloat16(0.f);
        g_tr2h[i]=z; g_tr2l[i]=z; g_trih[i]=z; g_tril[i]=z;
    }
    if (i < OO*OO) {
        int r = i / OO, c = i - r*OO;
        float w = (r == c) ? 0.f : iew_in[i];
        g_iew[i] = w;
        split3(w, g_iewh[i], g_iewm[i], g_iewl[i]);
    }
    if (i < OO) g_ediag[i] = eiw_in[i*OO + i];
}

// ---------------- CSR build ----------------
__global__ void k_csr(const float* __restrict__ W) {
    int wid  = (blockIdx.x * blockDim.x + threadIdx.x) >> 5;
    int lane = threadIdx.x & 31;
    if (wid >= NN) return;
    int cnt = 0;
    for (int base = 0; base < NN; base += 32) {
        float w = W[wid*NN + base + lane];
        unsigned m = __ballot_sync(0xffffffffu, w != 0.f);
        if (w != 0.f) {
            int pos = cnt + __popc(m & ((1u << lane) - 1u));
            g_nzcol[(size_t)wid*NN + pos] = base + lane;
            g_nzval[(size_t)wid*NN + pos] = w;
        }
        cnt += __popc(m);
    }
    if (lane == 0) g_nzcnt[wid] = cnt;
}

// ---------------- layer 1: all T steps ----------------
__global__ __launch_bounds__(256) void k_layer1_all(const float* __restrict__ x,
                                                    float* __restrict__ out_l1) {
    int idx = blockIdx.x * 256 + threadIdx.x;
    int b = idx >> 11;
    int n = idx & (NN - 1);
    int cnt = g_nzcnt[n];
    const int*   cp = g_nzcol + (size_t)n*NN;
    const float* vp = g_nzval + (size_t)n*NN;
    const float* xb = x + (size_t)b*TT*NN;
    float v = 0.f, tr = 0.f;
    for (int t = 0; t < TT; t++) {
        const float* xr = xb + (size_t)t*NN;
        float acc = 0.f;
        for (int j = 0; j < cnt; j++) acc = fmaf(xr[cp[j]], vp[j], acc);
        v = fmaf(ALPHA_F, v, acc);
        float s = (v > THRESH_F) ? 1.f : 0.f;
        v = (v > THRESH_F) ? 0.f : v;
        tr = fmaf(DEC_F, tr, __fmul_rn(CDEC_F, s));
        size_t o = ((size_t)b*TT + t)*NN + n;
        out_l1[o] = s;
        size_t ot = ((size_t)t*BB + b)*NN + n;
        g_l1b[ot] = __float2bfloat16(s);
        bf16 h, l; split2(tr, h, l);
        g_tr1h[ot] = h; g_tr1l[ot] = l;
    }
}

extern __shared__ __align__(16) char smem_raw[];

// ---------------- gemm work item (identical math to R8 k_gemm_mma) ----------------
// item: 0..319 -> qt = item & 7, mt = (item >> 3) & 1, chunk = item >> 4
__device__ __forceinline__ void gemm_item(int item, int t, int tm) {
    bf16* sA = (bf16*)smem_raw;        // [64][136]
    bf16* sB = sA + 64*136;            // [3][64][136]
    int chunk = item >> 4, qt = item & 7, mo = ((item >> 3) & 1) * 64;
    const bf16 *Asrc, *W0, *W1, *W2;
    size_t astride; int wstride, k0; float* part;
    if (chunk < SPLIT_A) {
        Asrc = g_l1b + (size_t)t*BB*NN; astride = NN; k0 = chunk*128;
        W0 = g_hwh; W1 = g_hwm; W2 = g_hwl; wstride = NN;
        part = g_pA + (size_t)chunk*BB*OO;
    } else {
        Asrc = g_bufb + tm*OO; astride = (size_t)DLY*OO; k0 = (chunk - SPLIT_A)*128;
        W0 = g_iewh; W1 = g_iewm; W2 = g_iewl; wstride = OO;
        part = g_pI + (size_t)(chunk - SPLIT_A)*BB*OO;
    }
    int q0 = qt*64;
    int tid = threadIdx.x;
    uint32_t sAu = s2u(sA), sBu = s2u(sB);

    const bf16* Ws[3] = {W0, W1, W2};
    #pragma unroll
    for (int i = 0; i < 4; i++) {
        int idx = tid + i*256;
        int r = idx >> 4, c8 = idx & 15;
        cpa16(sAu + (uint32_t)(r*136 + c8*8)*2u, Asrc + (size_t)(mo + r)*astride + k0 + c8*8);
    }
    #pragma unroll
    for (int s = 0; s < 3; s++) {
        #pragma unroll
        for (int i = 0; i < 4; i++) {
            int idx = tid + i*256;
            int r = idx >> 4, c8 = idx & 15;
            cpa16(sBu + (uint32_t)((s*64 + r)*136 + c8*8)*2u,
                  Ws[s] + (size_t)(q0 + r)*wstride + k0 + c8*8);
        }
    }
    cpa_commit_wait();
    __syncthreads();

    int w = tid >> 5, lane = tid & 31, g = lane >> 2, qi = lane & 3;
    int wm = w & 3, wn = w >> 2;
    int lr = lane & 7, lsel = lane >> 3;

    uint32_t a[8][4];
    int arow = 16*wm + lr + ((lsel & 1) ? 8 : 0);
    #pragma unroll
    for (int k16 = 0; k16 < 8; k16++) {
        int acol = k16*16 + ((lsel & 2) ? 8 : 0);
        uint32_t addr = sAu + (uint32_t)(arow*136 + acol)*2u;
        asm volatile("ldmatrix.sync.aligned.m8n8.x4.shared.b16 {%0,%1,%2,%3}, [%4];"
                     : "=r"(a[k16][0]), "=r"(a[k16][1]), "=r"(a[k16][2]), "=r"(a[k16][3])
                     : "r"(addr));
    }

    float acc[4][4];
    #pragma unroll
    for (int j = 0; j < 4; j++) { acc[j][0]=0.f; acc[j][1]=0.f; acc[j][2]=0.f; acc[j][3]=0.f; }

    int brow_base = wn*32 + lr;
    int bcol_off = (lane & 8) ? 8 : 0;
    #pragma unroll
    for (int s = 0; s < 3; s++) {
        #pragma unroll
        for (int k16 = 0; k16 < 8; k16++) {
            #pragma unroll
            for (int j = 0; j < 4; j++) {
                uint32_t b0, b1;
                uint32_t baddr = sBu + (uint32_t)((s*64 + brow_base + j*8)*136 + k16*16 + bcol_off)*2u;
                asm volatile("ldmatrix.sync.aligned.m8n8.x2.shared.b16 {%0,%1}, [%2];"
                             : "=r"(b0), "=r"(b1) : "r"(baddr));
                asm volatile(
                    "mma.sync.aligned.m16n8k16.row.col.f32.bf16.bf16.f32 "
                    "{%0,%1,%2,%3},{%4,%5,%6,%7},{%8,%9},{%0,%1,%2,%3};\n"
                    : "+f"(acc[j][0]), "+f"(acc[j][1]), "+f"(acc[j][2]), "+f"(acc[j][3])
                    : "r"(a[k16][0]), "r"(a[k16][1]), "r"(a[k16][2]), "r"(a[k16][3]),
                      "r"(b0), "r"(b1));
            }
        }
    }
    int m0 = mo + 16*wm + g;
    #pragma unroll
    for (int j = 0; j < 4; j++) {
        int qc = q0 + wn*32 + j*8 + qi*2;
        *(float2*)(part + (size_t)m0*OO + qc)       = make_float2(acc[j][0], acc[j][1]);
        *(float2*)(part + (size_t)(m0 + 8)*OO + qc) = make_float2(acc[j][2], acc[j][3]);
    }
}

// ---------------- epi work item (identical math to R8 k_epi, item = old blockIdx 0..63) ----------------
__device__ __forceinline__ void epi_item(int item, float* __restrict__ out_l2, int t, int tm) {
    __shared__ float sh[3][32][8];
    int qb = item * 8;
    int tq = threadIdx.x & 7;
    int tb = threadIdx.x >> 3;
    int q  = qb + tq;

    float r2 = 0.f, ri = 0.f, rd = 0.f;
    for (int j = 0; j < 4; j++) {
        int b  = tb + 32*j;
        int bo = b*OO + q;
        float l1v = 0.f, io = 0.f;
        #pragma unroll
        for (int s = 0; s < SPLIT_A; s++) l1v = __fadd_rn(l1v, g_pA[(size_t)s*BB*OO + bo]);
        #pragma unroll
        for (int s = 0; s < SPLIT_I; s++) io  = __fadd_rn(io,  g_pI[(size_t)s*BB*OO + bo]);
        float v = fmaf(ALPHA_F, g_v2[bo], __fadd_rn(l1v, -io));
        float s2 = (v > THRESH_F) ? 1.f : 0.f;
        g_v2[bo] = (v > THRESH_F) ? 0.f : v;
        out_l2[((size_t)b*TT + t)*OO + q] = s2;
        float t2 = fmaf(DEC_F, g_tr2[bo], __fmul_rn(CDEC_F, s2));
        g_tr2[bo] = t2;
        { bf16 h, l; split2(t2, h, l); g_tr2h[bo] = h; g_tr2l[bo] = l; }
        float inh_in = __fmul_rn(s2, g_ediag[q]);
        float vv = fmaf(ALPHA_F, g_vi[bo], inh_in);
        float si = (vv > THRESH_F) ? 1.f : 0.f;
        g_vi[bo] = (vv > THRESH_F) ? 0.f : vv;
        g_bufb[((size_t)b*DLY + tm)*OO + q] = __float2bfloat16(si);
        float ti = fmaf(DEC_F, g_tri[bo], __fmul_rn(CDEC_F, si));
        g_tri[bo] = ti;
        { bf16 h, l; split2(ti, h, l); g_trih[bo] = h; g_tril[bo] = l; }
        r2 += t2; ri += ti; rd = fmaf(ti, t2, rd);
    }
    sh[0][tb][tq] = r2; sh[1][tb][tq] = ri; sh[2][tb][tq] = rd;
    __syncthreads();
    if (tb == 0) {
        float s2 = 0.f, si = 0.f, sd = 0.f;
        for (int g = 0; g < 32; g++) { s2 += sh[0][g][tq]; si += sh[1][g][tq]; sd += sh[2][g][tq]; }
        float m2 = s2 * INVB_F, mi = si * INVB_F;
        g_mtr2[q] = m2;
        float e = g_ediag[q];
        float dw = fmaf(A_PLUS_F, __fmul_rn(sd, INVB_F),
                        -__fmul_rn(__fmul_rn(A_MINUS_F, e), mi));
        g_ediag[q] = __fadd_rn(e, dw);
    }
    __syncthreads();
}

// ---------------- plast work item (identical math to R8 k_plast_mma) ----------------
// item 0..319: px = item % 40, qy = item / 40
__device__ __forceinline__ void plast_item(int item, int t) {
    bf16* sAh = (bf16*)smem_raw;        // [b=128][72]
    bf16* sAl = sAh + 128*72;
    bf16* sB0 = sAl + 128*72;
    bf16* sB1 = sB0 + 128*72;
    int px = item % 40;
    int mode = (px >= 32);
    int p0 = (mode ? (px - 32) : px) * 64;
    int q0 = (item / 40) * 64;
    const bf16* preh = mode ? g_trih : (g_tr1h + (size_t)t*BB*NN);
    const bf16* prel = mode ? g_tril : (g_tr1l + (size_t)t*BB*NN);
    int P = mode ? OO : NN;
    float* W = mode ? g_iew : g_hw;
    bf16 *Wh = mode ? g_iewh : g_hwh, *Wm = mode ? g_iewm : g_hwm, *Wl = mode ? g_iewl : g_hwl;

    int tid = threadIdx.x;
    uint32_t sAhu = s2u(sAh), sAlu = s2u(sAl), sB0u = s2u(sB0), sB1u = s2u(sB1);

    #pragma unroll
    for (int i = 0; i < 4; i++) {
        int idx = tid + i*256;
        int b = idx >> 3, c8 = idx & 7;
        uint32_t so = (uint32_t)(b*72 + c8*8)*2u;
        cpa16(sAhu + so, g_tr2h + b*OO + q0 + c8*8);
        cpa16(sAlu + so, g_tr2l + b*OO + q0 + c8*8);
        cpa16(sB0u + so, preh + (size_t)b*P + p0 + c8*8);
        cpa16(sB1u + so, prel + (size_t)b*P + p0 + c8*8);
    }
    cpa_commit_wait();
    __syncthreads();

    int w = tid >> 5, lane = tid & 31, g = lane >> 2, qi = lane & 3;
    int r8 = lane & 7, sel = lane >> 3;

    float acc[4][4];
    #pragma unroll
    for (int mi = 0; mi < 4; mi++) { acc[mi][0]=0.f; acc[mi][1]=0.f; acc[mi][2]=0.f; acc[mi][3]=0.f; }

    #pragma unroll
    for (int k16 = 0; k16 < 8; k16++) {
        int kb16 = k16*16;
        int rrB = kb16 + ((sel & 1) ? 8 : 0) + r8;
        uint32_t bo = (uint32_t)(rrB*72 + w*8)*2u;
        uint32_t bh0, bh1, bl0, bl1;
        asm volatile("ldmatrix.sync.aligned.m8n8.x2.trans.shared.b16 {%0,%1}, [%2];"
                     : "=r"(bh0), "=r"(bh1) : "r"(sB0u + bo));
        asm volatile("ldmatrix.sync.aligned.m8n8.x2.trans.shared.b16 {%0,%1}, [%2];"
                     : "=r"(bl0), "=r"(bl1) : "r"(sB1u + bo));
        int rrA = kb16 + ((sel & 2) ? 8 : 0) + r8;
        #pragma unroll
        for (int mi = 0; mi < 4; mi++) {
            int cc = mi*16 + ((sel & 1) ? 8 : 0);
            uint32_t ao = (uint32_t)(rrA*72 + cc)*2u;
            #pragma unroll
            for (int as = 0; as < 2; as++) {
                uint32_t a0, a1, a2, a3;
                asm volatile("ldmatrix.sync.aligned.m8n8.x4.trans.shared.b16 {%0,%1,%2,%3}, [%4];"
                             : "=r"(a0), "=r"(a1), "=r"(a2), "=r"(a3)
                             : "r"((as ? sAlu : sAhu) + ao));
                asm volatile(
                    "mma.sync.aligned.m16n8k16.row.col.f32.bf16.bf16.f32 "
                    "{%0,%1,%2,%3},{%4,%5,%6,%7},{%8,%9},{%0,%1,%2,%3};\n"
                    : "+f"(acc[mi][0]), "+f"(acc[mi][1]), "+f"(acc[mi][2]), "+f"(acc[mi][3])
                    : "r"(a0), "r"(a1), "r"(a2), "r"(a3), "r"(bh0), "r"(bh1));
                asm volatile(
                    "mma.sync.aligned.m16n8k16.row.col.f32.bf16.bf16.f32 "
                    "{%0,%1,%2,%3},{%4,%5,%6,%7},{%8,%9},{%0,%1,%2,%3};\n"
                    : "+f"(acc[mi][0]), "+f"(acc[mi][1]), "+f"(acc[mi][2]), "+f"(acc[mi][3])
                    : "r"(a0), "r"(a1), "r"(a2), "r"(a3), "r"(bl0), "r"(bl1));
            }
        }
    }

    int pc = p0 + w*8 + qi*2;
    #pragma unroll
    for (int mi = 0; mi < 4; mi++) {
        #pragma unroll
        for (int half = 0; half < 2; half++) {
            int qq = q0 + mi*16 + g + half*8;
            float h0 = acc[mi][half*2 + 0], h1 = acc[mi][half*2 + 1];
            float mean = g_mtr2[qq];
            size_t wbase = (size_t)qq*P + pc;
            float2 wv = *(float2*)(W + wbase);
            float dw0 = fmaf(A_PLUS_F, __fmul_rn(h0, INVB_F),
                             -__fmul_rn(__fmul_rn(A_MINUS_F, wv.x), mean));
            float dw1 = fmaf(A_PLUS_F, __fmul_rn(h1, INVB_F),
                             -__fmul_rn(__fmul_rn(A_MINUS_F, wv.y), mean));
            float nw0 = __fadd_rn(wv.x, dw0);
            float nw1 = __fadd_rn(wv.y, dw1);
            if (mode && qq == pc)     nw0 = 0.f;
            if (mode && qq == pc + 1) nw1 = 0.f;
            *(float2*)(W + wbase) = make_float2(nw0, nw1);
            bf16 h, m, l, h2, m2, l2;
            split3(nw0, h, m, l);
            split3(nw1, h2, m2, l2);
            *(__nv_bfloat162*)(Wh + wbase) = __nv_bfloat162(h, h2);
            *(__nv_bfloat162*)(Wm + wbase) = __nv_bfloat162(m, m2);
            *(__nv_bfloat162*)(Wl + wbase) = __nv_bfloat162(l, l2);
        }
    }
}

// ---------------- persistent kernel: all 100 steps, grid barriers between phases ----------------
__global__ __launch_bounds__(256, 2) void k_persist(float* __restrict__ out_l2) {
    int bid = blockIdx.x;
    int gen = 0;
    for (int t = 0; t < TT; t++) {
        int tm = t % DLY;
        for (int it = bid; it < 320; it += NBLK) {
            gemm_item(it, t, tm);
            __syncthreads();
        }
        gridbar(gen);
        if (bid < 64) epi_item(bid, out_l2, t, tm);
        gridbar(gen);
        for (int it = bid; it < 320; it += NBLK) {
            plast_item(it, t);
            __syncthreads();
        }
        gridbar(gen);
    }
    if (bid == 0 && threadIdx.x == 0) g_bar = 0;   // reset for next graph replay
}

// ---------------- launch ----------------
extern "C" void kernel_launch(void* const* d_in, const int* in_sizes, int n_in,
                              void* d_out, int out_size) {
    const float* x      = (const float*)d_in[0];
    const float* win    = (const float*)d_in[1];
    const float* hw_in  = (const float*)d_in[2];
    const float* eiw_in = (const float*)d_in[3];
    const float* iew_in = (const float*)d_in[4];
    float* out_l1 = (float*)d_out;
    float* out_l2 = out_l1 + (size_t)BB*TT*NN;

    const int sm_bytes = 4 * 128*72 * 2;   // 73728 (covers gemm's 69632 too)
    cudaFuncSetAttribute(k_persist, cudaFuncAttributeMaxDynamicSharedMemorySize, sm_bytes);

    k_init<<<(OO*NN)/256, 256>>>(hw_in, eiw_in, iew_in);
    k_csr<<<256, 256>>>(win);
    k_layer1_all<<<(BB*NN)/256, 256>>>(x, out_l1);
    k_persist<<<NBLK, 256, sm_bytes>>>(out_l2);
}

// round 10
// speedup vs baseline: 1.0054x; 1.0054x over previous
#include <cuda_runtime.h>
#include <cuda_bf16.h>
#include <cstdint>

#define BB 128
#define TT 100
#define NN 2048
#define OO 512
#define DLY 10

#define ALPHA_F   0.90483741803595957316f   // exp(-1/10)
#define DEC_F     0.95122942450071400910f   // exp(-1/20)
#define CDEC_F    0.04877057549928599090f   // 1 - exp(-1/20)
#define THRESH_F  0.02f
#define A_PLUS_F  1e-4f
#define A_MINUS_F 1e-4f
#define INVB_F    0.0078125f                // 1/128, exact

#define SPLIT_A 16
#define SPLIT_I 4
#define NBLK 160

typedef __nv_bfloat16 bf16;

// ---------------- state ----------------
__device__ bf16  g_l1b [(size_t)TT*BB*NN];
__device__ bf16  g_tr1h[(size_t)TT*BB*NN];
__device__ bf16  g_tr1l[(size_t)TT*BB*NN];
__device__ float g_v2 [BB*OO];
__device__ float g_vi [BB*OO];
__device__ float g_tr2[BB*OO];
__device__ float g_tri[BB*OO];
__device__ bf16  g_tr2h[BB*OO], g_tr2l[BB*OO];
__device__ bf16  g_trih[BB*OO], g_tril[BB*OO];
__device__ bf16  g_bufb[BB*DLY*OO];
__device__ float g_hw [(size_t)OO*NN];
__device__ bf16  g_hwh[(size_t)OO*NN], g_hwm[(size_t)OO*NN], g_hwl[(size_t)OO*NN];
__device__ float g_iew[OO*OO];
__device__ bf16  g_iewh[OO*OO], g_iewm[OO*OO], g_iewl[OO*OO];
__device__ float g_ediag[OO];
__device__ float g_mtr2[OO];
__device__ float g_pA[SPLIT_A*BB*OO];
__device__ float g_pI[SPLIT_I*BB*OO];
__device__ int   g_nzcnt[NN];
__device__ int   g_nzcol[(size_t)NN*NN];
__device__ float g_nzval[(size_t)NN*NN];
__device__ int   g_bar;
__device__ int   g_done;

__device__ __forceinline__ void split3(float w, bf16& h, bf16& m, bf16& l) {
    h = __float2bfloat16(w);
    float r1 = __fadd_rn(w, -__bfloat162float(h));
    m = __float2bfloat16(r1);
    float r2 = __fadd_rn(r1, -__bfloat162float(m));
    l = __float2bfloat16(r2);
}
__device__ __forceinline__ void split2(float w, bf16& h, bf16& l) {
    h = __float2bfloat16(w);
    l = __float2bfloat16(__fadd_rn(w, -__bfloat162float(h)));
}
__device__ __forceinline__ uint32_t s2u(const void* p) {
    return (uint32_t)__cvta_generic_to_shared(p);
}
__device__ __forceinline__ void cpa16(uint32_t d, const void* s) {
    asm volatile("cp.async.ca.shared.global [%0], [%1], 16;\n" :: "r"(d), "l"(s));
}
__device__ __forceinline__ void cpa_commit_wait() {
    asm volatile("cp.async.commit_group;\n");
    asm volatile("cp.async.wait_group 0;\n");
}

// CG-style grid barrier: single-thread fence/arrive/spin, CTA barrier for cumulativity
__device__ __forceinline__ void gridbar(int& gen) {
    gen++;
    __syncthreads();
    if (threadIdx.x == 0) {
        __threadfence();                       // release: covers all CTA writes (via bar)
        atomicAdd(&g_bar, 1);
        int target = gen * NBLK;
        while (*((volatile int*)&g_bar) < target) __nanosleep(32);
        __threadfence();                       // acquire: invalidate stale L1 for this SM
    }
    __syncthreads();
}

// ---------------- init ----------------
__global__ void k_init(const float* __restrict__ hw_in,
                       const float* __restrict__ eiw_in,
                       const float* __restrict__ iew_in) {
    int i = blockIdx.x * blockDim.x + threadIdx.x;
    if (i < OO*NN) {
        float w = hw_in[i];
        g_hw[i] = w;
        split3(w, g_hwh[i], g_hwm[i], g_hwl[i]);
    }
    if (i < BB*DLY*OO) g_bufb[i] = __float2bfloat16(0.f);
    if (i < BB*OO) {
        g_v2[i]=0.f; g_vi[i]=0.f; g_tr2[i]=0.f; g_tri[i]=0.f;
        bf16 z = __float2bfloat16(0.f);
        g_tr2h[i]=z; g_tr2l[i]=z; g_trih[i]=z; g_tril[i]=z;
    }
    if (i < OO*OO) {
        int r = i / OO, c = i - r*OO;
        float w = (r == c) ? 0.f : iew_in[i];
        g_iew[i] = w;
        split3(w, g_iewh[i], g_iewm[i], g_iewl[i]);
    }
    if (i < OO) g_ediag[i] = eiw_in[i*OO + i];
}

// ---------------- CSR build ----------------
__global__ void k_csr(const float* __restrict__ W) {
    int wid  = (blockIdx.x * blockDim.x + threadIdx.x) >> 5;
    int lane = threadIdx.x & 31;
    if (wid >= NN) return;
    int cnt = 0;
    for (int base = 0; base < NN; base += 32) {
        float w = W[wid*NN + base + lane];
        unsigned m = __ballot_sync(0xffffffffu, w != 0.f);
        if (w != 0.f) {
            int pos = cnt + __popc(m & ((1u << lane) - 1u));
            g_nzcol[(size_t)wid*NN + pos] = base + lane;
            g_nzval[(size_t)wid*NN + pos] = w;
        }
        cnt += __popc(m);
    }
    if (lane == 0) g_nzcnt[wid] = cnt;
}

// ---------------- layer 1: all T steps ----------------
__global__ __launch_bounds__(256) void k_layer1_all(const float* __restrict__ x,
                                                    float* __restrict__ out_l1) {
    int idx = blockIdx.x * 256 + threadIdx.x;
    int b = idx >> 11;
    int n = idx & (NN - 1);
    int cnt = g_nzcnt[n];
    const int*   cp = g_nzcol + (size_t)n*NN;
    const float* vp = g_nzval + (size_t)n*NN;
    const float* xb = x + (size_t)b*TT*NN;
    float v = 0.f, tr = 0.f;
    for (int t = 0; t < TT; t++) {
        const float* xr = xb + (size_t)t*NN;
        float acc = 0.f;
        for (int j = 0; j < cnt; j++) acc = fmaf(xr[cp[j]], vp[j], acc);
        v = fmaf(ALPHA_F, v, acc);
        float s = (v > THRESH_F) ? 1.f : 0.f;
        v = (v > THRESH_F) ? 0.f : v;
        tr = fmaf(DEC_F, tr, __fmul_rn(CDEC_F, s));
        size_t o = ((size_t)b*TT + t)*NN + n;
        out_l1[o] = s;
        size_t ot = ((size_t)t*BB + b)*NN + n;
        g_l1b[ot] = __float2bfloat16(s);
        bf16 h, l; split2(tr, h, l);
        g_tr1h[ot] = h; g_tr1l[ot] = l;
    }
}

extern __shared__ __align__(16) char smem_raw[];

// ---------------- gemm item: m=128, 64q, one K-chunk of 128, 3 splits ----------------
// item 0..159: chunk = item >> 3, qt = item & 7
__device__ __forceinline__ void gemm_item(int item, int t, int tm) {
    bf16* sA = (bf16*)smem_raw;        // [128][136]
    bf16* sB = sA + 128*136;           // [3][64][136]
    int chunk = item >> 3, qt = item & 7;
    const bf16 *Asrc, *W0, *W1, *W2;
    size_t astride; int wstride, k0; float* part;
    if (chunk < SPLIT_A) {
        Asrc = g_l1b + (size_t)t*BB*NN; astride = NN; k0 = chunk*128;
        W0 = g_hwh; W1 = g_hwm; W2 = g_hwl; wstride = NN;
        part = g_pA + (size_t)chunk*BB*OO;
    } else {
        Asrc = g_bufb + tm*OO; astride = (size_t)DLY*OO; k0 = (chunk - SPLIT_A)*128;
        W0 = g_iewh; W1 = g_iewm; W2 = g_iewl; wstride = OO;
        part = g_pI + (size_t)(chunk - SPLIT_A)*BB*OO;
    }
    int q0 = qt*64;
    int tid = threadIdx.x;
    uint32_t sAu = s2u(sA), sBu = s2u(sB);

    const bf16* Ws[3] = {W0, W1, W2};
    #pragma unroll
    for (int i = 0; i < 8; i++) {
        int idx = tid + i*256;
        int r = idx >> 4, c8 = idx & 15;
        cpa16(sAu + (uint32_t)(r*136 + c8*8)*2u, Asrc + (size_t)r*astride + k0 + c8*8);
    }
    #pragma unroll
    for (int s = 0; s < 3; s++) {
        #pragma unroll
        for (int i = 0; i < 4; i++) {
            int idx = tid + i*256;
            int r = idx >> 4, c8 = idx & 15;
            cpa16(sBu + (uint32_t)((s*64 + r)*136 + c8*8)*2u,
                  Ws[s] + (size_t)(q0 + r)*wstride + k0 + c8*8);
        }
    }
    cpa_commit_wait();
    __syncthreads();

    int w = tid >> 5, lane = tid & 31, g = lane >> 2, qi = lane & 3;
    int lr = lane & 7, lsel = lane >> 3;

    // hoist A fragments (8 k16, reused across 3 splits)
    uint32_t a[8][4];
    int arow = 16*w + lr + ((lsel & 1) ? 8 : 0);
    #pragma unroll
    for (int k16 = 0; k16 < 8; k16++) {
        int acol = k16*16 + ((lsel & 2) ? 8 : 0);
        uint32_t addr = sAu + (uint32_t)(arow*136 + acol)*2u;
        asm volatile("ldmatrix.sync.aligned.m8n8.x4.shared.b16 {%0,%1,%2,%3}, [%4];"
                     : "=r"(a[k16][0]), "=r"(a[k16][1]), "=r"(a[k16][2]), "=r"(a[k16][3])
                     : "r"(addr));
    }

    float acc[8][4];
    #pragma unroll
    for (int j = 0; j < 8; j++) { acc[j][0]=0.f; acc[j][1]=0.f; acc[j][2]=0.f; acc[j][3]=0.f; }

    int bcol_off = (lane & 8) ? 8 : 0;
    #pragma unroll
    for (int s = 0; s < 3; s++) {
        #pragma unroll
        for (int k16 = 0; k16 < 8; k16++) {
            #pragma unroll
            for (int j = 0; j < 8; j++) {
                uint32_t b0, b1;
                uint32_t baddr = sBu + (uint32_t)((s*64 + lr + j*8)*136 + k16*16 + bcol_off)*2u;
                asm volatile("ldmatrix.sync.aligned.m8n8.x2.shared.b16 {%0,%1}, [%2];"
                             : "=r"(b0), "=r"(b1) : "r"(baddr));
                asm volatile(
                    "mma.sync.aligned.m16n8k16.row.col.f32.bf16.bf16.f32 "
                    "{%0,%1,%2,%3},{%4,%5,%6,%7},{%8,%9},{%0,%1,%2,%3};\n"
                    : "+f"(acc[j][0]), "+f"(acc[j][1]), "+f"(acc[j][2]), "+f"(acc[j][3])
                    : "r"(a[k16][0]), "r"(a[k16][1]), "r"(a[k16][2]), "r"(a[k16][3]),
                      "r"(b0), "r"(b1));
            }
        }
    }
    int m0 = 16*w + g;
    #pragma unroll
    for (int j = 0; j < 8; j++) {
        int qc = q0 + j*8 + qi*2;
        *(float2*)(part + (size_t)m0*OO + qc)       = make_float2(acc[j][0], acc[j][1]);
        *(float2*)(part + (size_t)(m0 + 8)*OO + qc) = make_float2(acc[j][2], acc[j][3]);
    }
}

// ---------------- epi item (identical math to R8) ----------------
__device__ __forceinline__ void epi_item(int item, float* __restrict__ out_l2, int t, int tm) {
    __shared__ float sh[3][32][8];
    int qb = item * 8;
    int tq = threadIdx.x & 7;
    int tb = threadIdx.x >> 3;
    int q  = qb + tq;

    float r2 = 0.f, ri = 0.f, rd = 0.f;
    for (int j = 0; j < 4; j++) {
        int b  = tb + 32*j;
        int bo = b*OO + q;
        float l1v = 0.f, io = 0.f;
        #pragma unroll
        for (int s = 0; s < SPLIT_A; s++) l1v = __fadd_rn(l1v, g_pA[(size_t)s*BB*OO + bo]);
        #pragma unroll
        for (int s = 0; s < SPLIT_I; s++) io  = __fadd_rn(io,  g_pI[(size_t)s*BB*OO + bo]);
        float v = fmaf(ALPHA_F, g_v2[bo], __fadd_rn(l1v, -io));
        float s2 = (v > THRESH_F) ? 1.f : 0.f;
        g_v2[bo] = (v > THRESH_F) ? 0.f : v;
        out_l2[((size_t)b*TT + t)*OO + q] = s2;
        float t2 = fmaf(DEC_F, g_tr2[bo], __fmul_rn(CDEC_F, s2));
        g_tr2[bo] = t2;
        { bf16 h, l; split2(t2, h, l); g_tr2h[bo] = h; g_tr2l[bo] = l; }
        float inh_in = __fmul_rn(s2, g_ediag[q]);
        float vv = fmaf(ALPHA_F, g_vi[bo], inh_in);
        float si = (vv > THRESH_F) ? 1.f : 0.f;
        g_vi[bo] = (vv > THRESH_F) ? 0.f : vv;
        g_bufb[((size_t)b*DLY + tm)*OO + q] = __float2bfloat16(si);
        float ti = fmaf(DEC_F, g_tri[bo], __fmul_rn(CDEC_F, si));
        g_tri[bo] = ti;
        { bf16 h, l; split2(ti, h, l); g_trih[bo] = h; g_tril[bo] = l; }
        r2 += t2; ri += ti; rd = fmaf(ti, t2, rd);
    }
    sh[0][tb][tq] = r2; sh[1][tb][tq] = ri; sh[2][tb][tq] = rd;
    __syncthreads();
    if (tb == 0) {
        float s2 = 0.f, si = 0.f, sd = 0.f;
        for (int g = 0; g < 32; g++) { s2 += sh[0][g][tq]; si += sh[1][g][tq]; sd += sh[2][g][tq]; }
        float m2 = s2 * INVB_F, mi = si * INVB_F;
        g_mtr2[q] = m2;
        float e = g_ediag[q];
        float dw = fmaf(A_PLUS_F, __fmul_rn(sd, INVB_F),
                        -__fmul_rn(__fmul_rn(A_MINUS_F, e), mi));
        g_ediag[q] = __fadd_rn(e, dw);
    }
    __syncthreads();
}

// ---------------- plast item: 64q x 128p tile ----------------
// item 0..159: 0..127 hw (px=item&15, qy=item>>4); 128..159 iew (px=i2&3, qy=i2>>2)
__device__ __forceinline__ void plast_item(int item, int t) {
    bf16* sAh = (bf16*)smem_raw;        // [b=128][72]  (tr2 hi)
    bf16* sAl = sAh + 128*72;
    bf16* sB0 = sAl + 128*72;           // [b=128][136] (pre hi, 128 p cols)
    bf16* sB1 = sB0 + 128*136;
    int mode, p0, q0;
    if (item < 128) { mode = 0; p0 = (item & 15) * 128; q0 = (item >> 4) * 64; }
    else { int i2 = item - 128; mode = 1; p0 = (i2 & 3) * 128; q0 = (i2 >> 2) * 64; }
    const bf16* preh = mode ? g_trih : (g_tr1h + (size_t)t*BB*NN);
    const bf16* prel = mode ? g_tril : (g_tr1l + (size_t)t*BB*NN);
    int P = mode ? OO : NN;
    float* W = mode ? g_iew : g_hw;
    bf16 *Wh = mode ? g_iewh : g_hwh, *Wm = mode ? g_iewm : g_hwm, *Wl = mode ? g_iewl : g_hwl;

    int tid = threadIdx.x;
    uint32_t sAhu = s2u(sAh), sAlu = s2u(sAl), sB0u = s2u(sB0), sB1u = s2u(sB1);

    #pragma unroll
    for (int i = 0; i < 4; i++) {
        int idx = tid + i*256;
        int b = idx >> 3, c8 = idx & 7;
        uint32_t so = (uint32_t)(b*72 + c8*8)*2u;
        cpa16(sAhu + so, g_tr2h + b*OO + q0 + c8*8);
        cpa16(sAlu + so, g_tr2l + b*OO + q0 + c8*8);
    }
    #pragma unroll
    for (int i = 0; i < 8; i++) {
        int idx = tid + i*256;
        int b = idx >> 4, c8 = idx & 15;
        uint32_t so = (uint32_t)(b*136 + c8*8)*2u;
        cpa16(sB0u + so, preh + (size_t)b*P + p0 + c8*8);
        cpa16(sB1u + so, prel + (size_t)b*P + p0 + c8*8);
    }
    cpa_commit_wait();
    __syncthreads();

    int w = tid >> 5, lane = tid & 31, g = lane >> 2, qi = lane & 3;
    int r8 = lane & 7, sel = lane >> 3;

    float acc[4][2][4];
    #pragma unroll
    for (int mi = 0; mi < 4; mi++)
        #pragma unroll
        for (int st = 0; st < 2; st++)
            { acc[mi][st][0]=0.f; acc[mi][st][1]=0.f; acc[mi][st][2]=0.f; acc[mi][st][3]=0.f; }

    #pragma unroll
    for (int k16 = 0; k16 < 8; k16++) {
        int kb16 = k16*16;
        int rrB = kb16 + ((sel & 1) ? 8 : 0) + r8;
        uint32_t bh[2][2], bl[2][2];
        #pragma unroll
        for (int st = 0; st < 2; st++) {
            uint32_t bo = (uint32_t)(rrB*136 + w*16 + st*8)*2u;
            asm volatile("ldmatrix.sync.aligned.m8n8.x2.trans.shared.b16 {%0,%1}, [%2];"
                         : "=r"(bh[st][0]), "=r"(bh[st][1]) : "r"(sB0u + bo));
            asm volatile("ldmatrix.sync.aligned.m8n8.x2.trans.shared.b16 {%0,%1}, [%2];"
                         : "=r"(bl[st][0]), "=r"(bl[st][1]) : "r"(sB1u + bo));
        }
        int rrA = kb16 + ((sel & 2) ? 8 : 0) + r8;
        #pragma unroll
        for (int mi = 0; mi < 4; mi++) {
            int cc = mi*16 + ((sel & 1) ? 8 : 0);
            uint32_t ao = (uint32_t)(rrA*72 + cc)*2u;
            #pragma unroll
            for (int as = 0; as < 2; as++) {
                uint32_t a0, a1, a2, a3;
                asm volatile("ldmatrix.sync.aligned.m8n8.x4.trans.shared.b16 {%0,%1,%2,%3}, [%4];"
                             : "=r"(a0), "=r"(a1), "=r"(a2), "=r"(a3)
                             : "r"((as ? sAlu : sAhu) + ao));
                #pragma unroll
                for (int st = 0; st < 2; st++) {
                    asm volatile(
                        "mma.sync.aligned.m16n8k16.row.col.f32.bf16.bf16.f32 "
                        "{%0,%1,%2,%3},{%4,%5,%6,%7},{%8,%9},{%0,%1,%2,%3};\n"
                        : "+f"(acc[mi][st][0]), "+f"(acc[mi][st][1]),
                          "+f"(acc[mi][st][2]), "+f"(acc[mi][st][3])
                        : "r"(a0), "r"(a1), "r"(a2), "r"(a3), "r"(bh[st][0]), "r"(bh[st][1]));
                    asm volatile(
                        "mma.sync.aligned.m16n8k16.row.col.f32.bf16.bf16.f32 "
                        "{%0,%1,%2,%3},{%4,%5,%6,%7},{%8,%9},{%0,%1,%2,%3};\n"
                        : "+f"(acc[mi][st][0]), "+f"(acc[mi][st][1]),
                          "+f"(acc[mi][st][2]), "+f"(acc[mi][st][3])
                        : "r"(a0), "r"(a1), "r"(a2), "r"(a3), "r"(bl[st][0]), "r"(bl[st][1]));
                }
            }
        }
    }

    #pragma unroll
    for (int mi = 0; mi < 4; mi++) {
        #pragma unroll
        for (int st = 0; st < 2; st++) {
            int pc = p0 + w*16 + st*8 + qi*2;
            #pragma unroll
            for (int half = 0; half < 2; half++) {
                int qq = q0 + mi*16 + g + half*8;
                float h0 = acc[mi][st][half*2 + 0], h1 = acc[mi][st][half*2 + 1];
                float mean = g_mtr2[qq];
                size_t wbase = (size_t)qq*P + pc;
                float2 wv = *(float2*)(W + wbase);
                float dw0 = fmaf(A_PLUS_F, __fmul_rn(h0, INVB_F),
                                 -__fmul_rn(__fmul_rn(A_MINUS_F, wv.x), mean));
                float dw1 = fmaf(A_PLUS_F, __fmul_rn(h1, INVB_F),
                                 -__fmul_rn(__fmul_rn(A_MINUS_F, wv.y), mean));
                float nw0 = __fadd_rn(wv.x, dw0);
                float nw1 = __fadd_rn(wv.y, dw1);
                if (mode && qq == pc)     nw0 = 0.f;
                if (mode && qq == pc + 1) nw1 = 0.f;
                *(float2*)(W + wbase) = make_float2(nw0, nw1);
                bf16 h, m, l, h2, m2, l2;
                split3(nw0, h, m, l);
                split3(nw1, h2, m2, l2);
                *(__nv_bfloat162*)(Wh + wbase) = __nv_bfloat162(h, h2);
                *(__nv_bfloat162*)(Wm + wbase) = __nv_bfloat162(m, m2);
                *(__nv_bfloat162*)(Wl + wbase) = __nv_bfloat162(l, l2);
            }
        }
    }
}

// ---------------- persistent kernel ----------------
__global__ __launch_bounds__(256, 2) void k_persist(float* __restrict__ out_l2) {
    int bid = blockIdx.x;
    int gen = 0;
    for (int t = 0; t < TT; t++) {
        int tm = t % DLY;
        gemm_item(bid, t, tm);
        __syncthreads();
        gridbar(gen);
        if (bid < 64) epi_item(bid, out_l2, t, tm);
        gridbar(gen);
        plast_item(bid, t);
        __syncthreads();
        gridbar(gen);
    }
    // replay-safe reset handshake
    __syncthreads();
    if (threadIdx.x == 0) {
        __threadfence();
        atomicAdd(&g_done, 1);
        if (bid == 0) {
            while (*((volatile int*)&g_done) < NBLK) __nanosleep(32);
            g_bar = 0;
            g_done = 0;
            __threadfence();
        }
    }
}

// ---------------- launch ----------------
extern "C" void kernel_launch(void* const* d_in, const int* in_sizes, int n_in,
                              void* d_out, int out_size) {
    const float* x      = (const float*)d_in[0];
    const float* win    = (const float*)d_in[1];
    const float* hw_in  = (const float*)d_in[2];
    const float* eiw_in = (const float*)d_in[3];
    const float* iew_in = (const float*)d_in[4];
    float* out_l1 = (float*)d_out;
    float* out_l2 = out_l1 + (size_t)BB*TT*NN;

    // smem: max(gemm 128*136 + 3*64*136, plast 2*128*72 + 2*128*136) bf16
    const int sm_bytes = (2*128*72 + 2*128*136) * 2;   // 106496
    cudaFuncSetAttribute(k_persist, cudaFuncAttributeMaxDynamicSharedMemorySize, sm_bytes);

    k_init<<<(OO*NN)/256, 256>>>(hw_in, eiw_in, iew_in);
    k_csr<<<256, 256>>>(win);
    k_layer1_all<<<(BB*NN)/256, 256>>>(x, out_l1);
    k_persist<<<NBLK, 256, sm_bytes>>>(out_l2);
}